// round 3
// baseline (speedup 1.0000x reference)
#include <cuda_runtime.h>

#define BB   64
#define TT   512
#define DD   256
#define WW   50
#define BAND 104          // padded band width (101 -> 104)
#define BIGF 1e9f

#define TI 16
#define TJ 128
#define KC 32

// scratch (no allocations allowed -> __device__ globals)
__device__ float g_cost[(size_t)BB * TT * BAND];   // ~13.6 MB, L2-resident
__device__ float g_rn1[BB * TT];
__device__ float g_rn2[BB * TT];

// ---------------------------------------------------------------------------
// Kernel 1: reciprocal norms  rn = 1 / max(||x||, eps)
// one warp per row, 2*B*T rows
// ---------------------------------------------------------------------------
__global__ void norm_kernel(const float* __restrict__ x1,
                            const float* __restrict__ x2) {
    int warp = (blockIdx.x * blockDim.x + threadIdx.x) >> 5;
    int lane = threadIdx.x & 31;
    if (warp >= 2 * BB * TT) return;
    const float* src;
    float* dst;
    if (warp < BB * TT) { src = x1 + (size_t)warp * DD;            dst = g_rn1 + warp; }
    else                { src = x2 + (size_t)(warp - BB*TT) * DD;  dst = g_rn2 + (warp - BB*TT); }
    const float4* p4 = (const float4*)src;
    float4 a = p4[lane];
    float4 c = p4[lane + 32];
    float s = a.x*a.x + a.y*a.y + a.z*a.z + a.w*a.w
            + c.x*c.x + c.y*c.y + c.z*c.z + c.w*c.w;
    #pragma unroll
    for (int o = 16; o > 0; o >>= 1) s += __shfl_xor_sync(0xffffffffu, s, o);
    if (lane == 0) *dst = 1.0f / fmaxf(sqrtf(s), 1e-8f);
}

// ---------------------------------------------------------------------------
// Kernel 2: banded cost  g_cost[b][i][j-i+W] = 1 - <x1_i, x2_j> * rn1_i * rn2_j
// block tile: 16 i x 128 j (covers the 116-wide j-window of an i-tile)
// 128 threads, 4x4 micro-tiles, fp32 FFMA
// ---------------------------------------------------------------------------
__global__ void cost_kernel(const float* __restrict__ x1,
                            const float* __restrict__ x2) {
    __shared__ float As[KC][TI];
    __shared__ float Bs[KC][TJ];

    int b  = blockIdx.y;
    int i0 = blockIdx.x * TI;
    int j0 = i0 - 56;                   // window [i0-56, i0+71] superset of band
    int tid = threadIdx.x;              // 128 threads
    int tj = tid & 31;
    int ti = tid >> 5;

    const float* X1 = x1 + (size_t)b * TT * DD;
    const float* X2 = x2 + (size_t)b * TT * DD;

    // load-index decomposition
    int arow = tid & 15;                // x1 row within tile
    int ak   = (tid >> 4) << 2;         // k-offset (0,4,...,28)
    int jb   = j0 + tid;                // x2 row (one per thread)
    int jb_c = min(max(jb, 0), TT - 1); // clamp (masked at store)

    float acc[4][4] = {};

    for (int kc = 0; kc < DD; kc += KC) {
        __syncthreads();
        // x1 tile -> As (transposed: As[k][i])
        float4 av = *(const float4*)(X1 + (size_t)(i0 + arow) * DD + kc + ak);
        As[ak+0][arow] = av.x; As[ak+1][arow] = av.y;
        As[ak+2][arow] = av.z; As[ak+3][arow] = av.w;
        // x2 tile -> Bs (transposed: Bs[k][j])
        const float* xr = X2 + (size_t)jb_c * DD + kc;
        #pragma unroll
        for (int q = 0; q < KC/4; q++) {
            float4 bv = *(const float4*)(xr + q*4);
            Bs[q*4+0][tid] = bv.x; Bs[q*4+1][tid] = bv.y;
            Bs[q*4+2][tid] = bv.z; Bs[q*4+3][tid] = bv.w;
        }
        __syncthreads();
        #pragma unroll
        for (int k = 0; k < KC; k++) {
            float4 a4 = *(const float4*)&As[k][ti*4];
            float4 b4 = *(const float4*)&Bs[k][tj*4];
            float ar[4] = {a4.x, a4.y, a4.z, a4.w};
            float br[4] = {b4.x, b4.y, b4.z, b4.w};
            #pragma unroll
            for (int ii = 0; ii < 4; ii++)
                #pragma unroll
                for (int jj = 0; jj < 4; jj++)
                    acc[ii][jj] = fmaf(ar[ii], br[jj], acc[ii][jj]);
        }
    }

    // masked band store
    #pragma unroll
    for (int ii = 0; ii < 4; ii++) {
        int i = i0 + ti*4 + ii;
        float r1 = g_rn1[b*TT + i];
        #pragma unroll
        for (int jj = 0; jj < 4; jj++) {
            int j = j0 + tj*4 + jj;
            int k = j - i + WW;
            if (j >= 0 && j < TT && k >= 0 && k <= 2*WW) {
                float r2 = g_rn2[b*TT + j];
                g_cost[(size_t)(b*TT + i) * BAND + k] = 1.0f - acc[ii][jj] * r1 * r2;
            }
        }
    }
}

// ---------------------------------------------------------------------------
// Kernel 3: banded DTW wavefront DP, one block (64 threads) per batch
// 3 rotating diagonal buffers in shared; cost prefetched 8 diagonals ahead
// into per-thread registers so the 1023-step chain never stalls on L2.
// ---------------------------------------------------------------------------
__global__ void dtw_kernel(float* __restrict__ out) {
    __shared__ float buf[3][TT + 2];   // index i+1 holds row i; [0] is i=-1 (=BIG)
    int b = blockIdx.x;
    int t = threadIdx.x;               // 64 threads, <=51 active per diagonal

    for (int idx = t; idx < 3 * (TT + 2); idx += 64)
        ((float*)buf)[idx] = BIGF;
    __syncthreads();

    float* p2  = buf[0];
    float* p1  = buf[1];
    float* cur = buf[2];
    const float* cb = g_cost + (size_t)b * TT * BAND;

    const int NDIAG = 2 * TT - 1;      // 1023

    // prefetch queue: cq[s] holds cost for this thread on diagonal (dbase+s)
    float cq[8];
    #pragma unroll
    for (int s = 0; s < 8; s++) {
        int d = s;
        int ilo = max(0, max(d - (TT-1), (d - (WW-1)) >> 1));
        int ihi = min(TT-1, min(d, (d + WW) >> 1));
        int i = ilo + t;
        cq[s] = (i <= ihi) ? cb[i * BAND + (d - 2*i + WW)] : BIGF;
    }

    for (int dbase = 0; dbase < NDIAG; dbase += 8) {
        #pragma unroll
        for (int s = 0; s < 8; s++) {
            int d = dbase + s;
            if (d < NDIAG) {
                int ilo = max(0, max(d - (TT-1), (d - (WW-1)) >> 1));
                int ihi = min(TT-1, min(d, (d + WW) >> 1));
                int i = ilo + t;
                bool valid = (i <= ihi);
                float c = cq[s];
                // prefetch cost for diagonal d+8 (same thread->i mapping rule)
                int dp = d + 8;
                if (dp < NDIAG) {
                    int plo = max(0, max(dp - (TT-1), (dp - (WW-1)) >> 1));
                    int phi = min(TT-1, min(dp, (dp + WW) >> 1));
                    int pi = plo + t;
                    if (pi <= phi) cq[s] = cb[pi * BAND + (dp - 2*pi + WW)];
                }
                if (valid) {
                    // prev1[i] = p1[i+1], prev1[i-1] = p1[i], prev2[i-1] = p2[i]
                    float m = fminf(fminf(p1[i+1], p1[i]), p2[i]);
                    if (d == 0) m = 0.0f;                 // DP origin (0,0)
                    float v = c + m;
                    cur[i + 1] = v;
                    if (d == NDIAG - 1 && i == TT - 1) out[b] = v;
                }
                if (t == 0) {                             // band-edge sentinels
                    cur[ilo] = BIGF;
                    cur[ihi + 2] = BIGF;
                }
            }
            __syncthreads();
            float* tmp = p2; p2 = p1; p1 = cur; cur = tmp;
        }
    }
}

// ---------------------------------------------------------------------------
extern "C" void kernel_launch(void* const* d_in, const int* in_sizes, int n_in,
                              void* d_out, int out_size) {
    const float* x1 = (const float*)d_in[0];
    const float* x2 = (const float*)d_in[1];
    float* out = (float*)d_out;

    norm_kernel<<<(2 * BB * TT) / 8, 256>>>(x1, x2);
    dim3 g(TT / TI, BB);
    cost_kernel<<<g, 128>>>(x1, x2);
    dtw_kernel<<<BB, 64>>>(out);
}